// round 14
// baseline (speedup 1.0000x reference)
#include <cuda_runtime.h>

// Fixed problem dims
#define TT 128
#define BB 256
#define II 1024
#define HH 2048
#define OO 10

#define MM (TT*BB)   // 32768
#define NN HH        // 2048
#define KK II        // 1024

#define BM 128
#define BN 128
#define BKD 16
#define NT (KK/BKD)      // 64
#define HALF_KT (NT/2)   // slice boundary: kt 0..31 -> k 0..511

typedef unsigned long long u64;

// ---- exact-rounding scalar helpers (immune to fast-math / re-contraction) ----
__device__ __forceinline__ float fadd(float a, float b) {
    float d; asm("add.rn.f32 %0,%1,%2;" : "=f"(d) : "f"(a), "f"(b)); return d;
}
__device__ __forceinline__ float fsub(float a, float b) {
    float d; asm("sub.rn.f32 %0,%1,%2;" : "=f"(d) : "f"(a), "f"(b)); return d;
}
__device__ __forceinline__ float ffma(float a, float b, float c) {
    float d; asm("fma.rn.f32 %0,%1,%2,%3;" : "=f"(d) : "f"(a), "f"(b), "f"(c)); return d;
}
__device__ __forceinline__ void fma2(u64 &d, u64 a, u64 b) {
    // packed fp32x2 FMA: two independent correctly-rounded fp32 FMAs
    asm volatile("fma.rn.f32x2 %0, %1, %2, %0;" : "+l"(d) : "l"(a), "l"(b));
}
__device__ __forceinline__ u64 add2(u64 a, u64 b) {
    u64 d; asm("add.rn.f32x2 %0,%1,%2;" : "=l"(d) : "l"(a), "l"(b)); return d;
}

// ---------------------------------------------------------------------------
// GEMM1: C[M,N] = X[M,K] * W1[N,K]^T, epilogue (dot + b1) + bias1.
// Reduction order (FROZEN — matches reference bit-exactly):
//   dot = chain(k=0..511) + chain(k=512..1023), each chain a serial
//   ascending-k FFMA sequence with a single accumulator.
// 128x128 CTA tile, 512 threads, per-thread 4(m) x 8(n). A is stored
// PRE-DUPLICATED in smem ({a,a} pairs) so the inner loop is pure
// LDS.128 + FFMA2 with zero MOVs. Double-buffered smem, one sync per k-tile.
// Smem: As 2*16*256*4 = 32KB + Bs 2*16*128*4 = 16KB = 48KB exactly.
// ---------------------------------------------------------------------------
__global__ __launch_bounds__(512)
void gemm1_kernel(const float* __restrict__ A,
                  const float* __restrict__ Bw,
                  const float* __restrict__ b1,
                  const float* __restrict__ bias1,
                  float* __restrict__ C)
{
    __shared__ float As[2][BKD][2*BM];   // duplicated pairs
    __shared__ float Bs[2][BKD][BN];

    const int tid = threadIdx.x;
    const int bm = blockIdx.y;
    const int bn = blockIdx.x;

    const float* Ag = A  + (size_t)bm * BM * KK;
    const float* Bg = Bw + (size_t)bn * BN * KK;

    const int frow = tid >> 2;        // 0..127 (fill row for A and B)
    const int kq   = (tid & 3) * 4;   // float4 slot within 16-wide k slab

    // prologue: fill stage 0 (one float4 of A and one of B per thread)
    {
        float4 a = *(const float4*)(Ag + (size_t)frow * KK + kq);
        float4 w = *(const float4*)(Bg + (size_t)frow * KK + kq);
        float va[4] = {a.x, a.y, a.z, a.w};
        float wa[4] = {w.x, w.y, w.z, w.w};
        #pragma unroll
        for (int j = 0; j < 4; j++) {
            ((float2*)As[0][kq + j])[frow] = make_float2(va[j], va[j]);
            Bs[0][kq + j][frow] = wa[j];
        }
    }
    __syncthreads();

    u64 ch[4][4];    // current slice's serial chain (4 m x 4 n-pairs)
    u64 tot[4][4];   // completed first-slice partial
    #pragma unroll
    for (int i = 0; i < 4; i++)
        #pragma unroll
        for (int j = 0; j < 4; j++) { ch[i][j] = 0ull; tot[i][j] = 0ull; }

    const int tm  = (tid >> 4) * 4;   // 0..124
    const int tn0 = (tid & 15) * 4;   // 0..60  (n group 0)
    const int tn1 = tn0 + 64;         // 64..124 (n group 1)

    for (int kt = 0; kt < NT; kt++) {
        const int cur = kt & 1;
        const int nxt = cur ^ 1;

        // issue next tile's global loads early (hidden under compute)
        float4 pa, pb;
        const bool more = (kt + 1 < NT);
        if (more) {
            const size_t off = (size_t)(kt + 1) * BKD + kq;
            pa = *(const float4*)(Ag + (size_t)frow * KK + off);
            pb = *(const float4*)(Bg + (size_t)frow * KK + off);
        }

        #pragma unroll
        for (int k = 0; k < BKD; k++) {          // strictly ascending k in slice
            // A: two 16B broadcast loads of pre-duplicated {a,a} pairs
            const ulonglong2* ap = (const ulonglong2*)&As[cur][k][2*tm];
            ulonglong2 q0 = ap[0], q1 = ap[1];
            u64 a2[4];
            a2[0] = q0.x; a2[1] = q0.y; a2[2] = q1.x; a2[3] = q1.y;
            // B: two lane-contiguous LDS.128 (2 wavefronts each, 100% useful)
            float4 bf0 = *(const float4*)&Bs[cur][k][tn0];
            float4 bf1 = *(const float4*)&Bs[cur][k][tn1];
            u64 b2[4];
            b2[0] = *(u64*)&bf0.x;  b2[1] = *(u64*)&bf0.z;
            b2[2] = *(u64*)&bf1.x;  b2[3] = *(u64*)&bf1.z;
            #pragma unroll
            for (int mi = 0; mi < 4; mi++)
                #pragma unroll
                for (int nj = 0; nj < 4; nj++)
                    fma2(ch[mi][nj], a2[mi], b2[nj]);
        }

        if (kt == HALF_KT - 1) {
            // end of slice 0: bank the partial, restart the chain for slice 1
            #pragma unroll
            for (int mi = 0; mi < 4; mi++)
                #pragma unroll
                for (int nj = 0; nj < 4; nj++) {
                    tot[mi][nj] = ch[mi][nj];
                    ch[mi][nj]  = 0ull;
                }
        }

        if (more) {
            // store into the other buffer (disjoint from the one just read;
            // end-of-iteration barrier orders its reuse)
            float va[4] = {pa.x, pa.y, pa.z, pa.w};
            float wa[4] = {pb.x, pb.y, pb.z, pb.w};
            #pragma unroll
            for (int j = 0; j < 4; j++) {
                ((float2*)As[nxt][kq + j])[frow] = make_float2(va[j], va[j]);
                Bs[nxt][kq + j][frow] = wa[j];
            }
            __syncthreads();
        }
    }

    // combine slices: dot = slice0 + slice1 (single correctly-rounded add)
    // then epilogue: (dot + b1) + bias1 — left-assoc
    const float bsc = bias1[0];
    const int gn0 = bn * BN + tn0;
    const int gn1 = bn * BN + tn1;
    float b1v[8];
    #pragma unroll
    for (int j = 0; j < 4; j++) { b1v[j] = b1[gn0 + j]; b1v[4 + j] = b1[gn1 + j]; }

    #pragma unroll
    for (int mi = 0; mi < 4; mi++) {
        const size_t gm = (size_t)bm * BM + tm + mi;
        float o[8];
        #pragma unroll
        for (int nj = 0; nj < 4; nj++) {
            u64 dot2 = add2(tot[mi][nj], ch[mi][nj]);   // p0 + p1
            float2 f = *reinterpret_cast<float2*>(&dot2);
            o[2*nj]   = fadd(fadd(f.x, b1v[2*nj]),   bsc);
            o[2*nj+1] = fadd(fadd(f.y, b1v[2*nj+1]), bsc);
        }
        *(float4*)(C + gm * NN + gn0) = make_float4(o[0], o[1], o[2], o[3]);
        *(float4*)(C + gm * NN + gn1) = make_float4(o[4], o[5], o[6], o[7]);
    }
}

// ---------------------------------------------------------------------------
// LIF scan, plain fp32, FMA-CONTRACTED (FROZEN — matches reference):
//   mem = fma(beta, mem, cur) - reset ; spk = (mem - 1 > 0)
// ---------------------------------------------------------------------------
__device__ __forceinline__ void lif_scan(float* p, size_t stride, float beta)
{
    float mem = 0.f;
    #pragma unroll 8
    for (int t = 0; t < TT; t++) {
        float c = p[(size_t)t * stride];
        float r = (mem > 1.0f) ? 1.0f : 0.0f;   // reset from previous mem
        mem = fsub(ffma(beta, mem, c), r);      // fma(B,mem,cur) - reset
        p[(size_t)t * stride] = (fsub(mem, 1.0f) > 0.f) ? 1.0f : 0.0f;
    }
}

__global__ void scan1_kernel(float* __restrict__ out)
{
    const int idx = blockIdx.x * blockDim.x + threadIdx.x;  // < B*H
    lif_scan(out + idx, (size_t)BB * HH, 0.9f);
}

__global__ void scan2_kernel(float* __restrict__ out2)
{
    const int idx = blockIdx.x * blockDim.x + threadIdx.x;
    if (idx >= BB * OO) return;
    lif_scan(out2 + idx, (size_t)BB * OO, 0.8f);
}

// ---------------------------------------------------------------------------
// GEMM2: cur2[M,10] = spk1[M,2048] * W2[10,2048]^T + b2.
// One row per thread, single accumulator, ascending-k FFMA chain (FROZEN),
// epilogue dot + b2. K tiled through smem (memory-bound on spk1 read).
// ---------------------------------------------------------------------------
#define BK2 64
__global__ __launch_bounds__(128)
void gemm2_kernel(const float* __restrict__ S,
                  const float* __restrict__ W2,
                  const float* __restrict__ b2,
                  float* __restrict__ C2)
{
    __shared__ float Ss[128][BK2 + 1];   // +1 pad -> conflict-free column reads
    __shared__ float Ws[BK2][OO];

    const int tid = threadIdx.x;
    const size_t row0 = (size_t)blockIdx.x * 128;

    float acc[OO];
    #pragma unroll
    for (int o = 0; o < OO; o++) acc[o] = 0.f;

    for (int kc = 0; kc < HH; kc += BK2) {       // ascending k blocks
        __syncthreads();
        #pragma unroll
        for (int i = 0; i < 16; i++) {           // 128x64 floats, float4 coalesced
            int f  = i * 128 + tid;
            int r  = f >> 4;
            int c4 = (f & 15) * 4;
            float4 v = *(const float4*)(S + (row0 + r) * (size_t)HH + kc + c4);
            Ss[r][c4]   = v.x;
            Ss[r][c4+1] = v.y;
            Ss[r][c4+2] = v.z;
            Ss[r][c4+3] = v.w;
        }
        #pragma unroll
        for (int i = 0; i < 5; i++) {            // 640 = 64*10 W2 elems
            int idx = i * 128 + tid;
            int k = idx / OO, o = idx % OO;
            Ws[k][o] = W2[(size_t)o * HH + kc + k];
        }
        __syncthreads();
        #pragma unroll 4
        for (int k = 0; k < BK2; k++) {          // ascending k within block
            float s = Ss[tid][k];
            #pragma unroll
            for (int o = 0; o < OO; o++)
                acc[o] = ffma(s, Ws[k][o], acc[o]);
        }
    }
    #pragma unroll
    for (int o = 0; o < OO; o++)
        C2[(row0 + tid) * OO + o] = fadd(acc[o], b2[o]);
}

// ---------------------------------------------------------------------------
// d_in order (setup_inputs dict order): x, W1, b1, bias1, W2, b2, T
// d_out layout: spk1_rec [T,B,H] followed by spk2_rec [T,B,O]
// ---------------------------------------------------------------------------
extern "C" void kernel_launch(void* const* d_in, const int* in_sizes, int n_in,
                              void* d_out, int out_size)
{
    const float* x     = (const float*)d_in[0];
    const float* W1    = (const float*)d_in[1];
    const float* b1    = (const float*)d_in[2];
    const float* bias1 = (const float*)d_in[3];
    const float* W2    = (const float*)d_in[4];
    const float* b2    = (const float*)d_in[5];

    float* out  = (float*)d_out;
    float* out2 = out + (size_t)TT * BB * HH;

    dim3 g1(NN / BN, MM / BM);                 // (16, 256)
    gemm1_kernel<<<g1, 512>>>(x, W1, b1, bias1, out);
    scan1_kernel<<<(BB * HH) / 256, 256>>>(out);
    gemm2_kernel<<<MM / 128, 128>>>(out, W2, b2, out2);
    scan2_kernel<<<(BB * OO + 255) / 256, 256>>>(out2);
}

// round 15
// speedup vs baseline: 1.2186x; 1.2186x over previous
#include <cuda_runtime.h>

// Fixed problem dims
#define TT 128
#define BB 256
#define II 1024
#define HH 2048
#define OO 10

#define MM (TT*BB)   // 32768
#define NN HH        // 2048
#define KK II        // 1024

#define BM 128
#define BN 128
#define BKD 16
#define NT (KK/BKD)      // 64
#define HALF_KT (NT/2)   // slice boundary: kt 0..31 -> k 0..511

typedef unsigned long long u64;

// ---- exact-rounding scalar helpers (immune to fast-math / re-contraction) ----
__device__ __forceinline__ float fadd(float a, float b) {
    float d; asm("add.rn.f32 %0,%1,%2;" : "=f"(d) : "f"(a), "f"(b)); return d;
}
__device__ __forceinline__ float fsub(float a, float b) {
    float d; asm("sub.rn.f32 %0,%1,%2;" : "=f"(d) : "f"(a), "f"(b)); return d;
}
__device__ __forceinline__ float ffma(float a, float b, float c) {
    float d; asm("fma.rn.f32 %0,%1,%2,%3;" : "=f"(d) : "f"(a), "f"(b), "f"(c)); return d;
}
__device__ __forceinline__ void fma2(u64 &d, u64 a, u64 b) {
    // packed fp32x2 FMA: two independent correctly-rounded fp32 FMAs
    asm volatile("fma.rn.f32x2 %0, %1, %2, %0;" : "+l"(d) : "l"(a), "l"(b));
}
__device__ __forceinline__ u64 add2(u64 a, u64 b) {
    u64 d; asm("add.rn.f32x2 %0,%1,%2;" : "=l"(d) : "l"(a), "l"(b)); return d;
}
__device__ __forceinline__ u64 dup2(float a) {
    // {a, a} register pair (ALU-pipe MOV, hides under FMA issue stream)
    u64 d; asm("mov.b64 %0, {%1, %1};" : "=l"(d) : "f"(a)); return d;
}

// ---------------------------------------------------------------------------
// GEMM1: C[M,N] = X[M,K] * W1[N,K]^T, epilogue (dot + b1) + bias1.
// Reduction order (FROZEN — matches reference bit-exactly):
//   dot = chain(k=0..511) + chain(k=512..1023), each chain a serial
//   ascending-k FFMA sequence with a single accumulator.
// 128x128 CTA tile, 512 threads, per-thread 4(m) x 8(n) where the 8 n-values
// are two lane-contiguous groups of 4 ((lane&15)*4 and +64) so B LDS.128s
// are 100%-efficient wavefronts. Double-buffered smem, one sync per k-tile.
// ---------------------------------------------------------------------------
__global__ __launch_bounds__(512)
void gemm1_kernel(const float* __restrict__ A,
                  const float* __restrict__ Bw,
                  const float* __restrict__ b1,
                  const float* __restrict__ bias1,
                  float* __restrict__ C)
{
    __shared__ float As[2][BKD][BM];
    __shared__ float Bs[2][BKD][BN];

    const int tid = threadIdx.x;
    const int bm = blockIdx.y;
    const int bn = blockIdx.x;

    const float* Ag = A  + (size_t)bm * BM * KK;
    const float* Bg = Bw + (size_t)bn * BN * KK;

    const int frow = tid >> 2;        // 0..127 (fill row for A and B)
    const int kq   = (tid & 3) * 4;   // float4 slot within 16-wide k slab

    // prologue: fill stage 0 (one float4 of A and one of B per thread)
    {
        float4 a = *(const float4*)(Ag + (size_t)frow * KK + kq);
        float4 w = *(const float4*)(Bg + (size_t)frow * KK + kq);
        float va[4] = {a.x, a.y, a.z, a.w};
        float wa[4] = {w.x, w.y, w.z, w.w};
        #pragma unroll
        for (int j = 0; j < 4; j++) {
            As[0][kq + j][frow] = va[j];
            Bs[0][kq + j][frow] = wa[j];
        }
    }
    __syncthreads();

    u64 ch[4][4];    // current slice's serial chain (4 m x 4 n-pairs)
    u64 tot[4][4];   // completed first-slice partial
    #pragma unroll
    for (int i = 0; i < 4; i++)
        #pragma unroll
        for (int j = 0; j < 4; j++) { ch[i][j] = 0ull; tot[i][j] = 0ull; }

    const int tm  = (tid >> 4) * 4;   // 0..124
    const int tn0 = (tid & 15) * 4;   // 0..60  (n group 0)
    const int tn1 = tn0 + 64;         // 64..124 (n group 1)

    for (int kt = 0; kt < NT; kt++) {
        const int cur = kt & 1;
        const int nxt = cur ^ 1;

        // issue next tile's global loads early (hidden under compute)
        float4 pa, pb;
        const bool more = (kt + 1 < NT);
        if (more) {
            const size_t off = (size_t)(kt + 1) * BKD + kq;
            pa = *(const float4*)(Ag + (size_t)frow * KK + off);
            pb = *(const float4*)(Bg + (size_t)frow * KK + off);
        }

        #pragma unroll
        for (int k = 0; k < BKD; k++) {          // strictly ascending k in slice
            // A: one 16B broadcast load (2 addrs/warp -> 1 wavefront), dup pairs
            float4 af = *(const float4*)&As[cur][k][tm];
            u64 a2[4];
            a2[0] = dup2(af.x); a2[1] = dup2(af.y);
            a2[2] = dup2(af.z); a2[3] = dup2(af.w);
            // B: two lane-contiguous LDS.128 (2 wavefronts each, 100% useful)
            float4 bf0 = *(const float4*)&Bs[cur][k][tn0];
            float4 bf1 = *(const float4*)&Bs[cur][k][tn1];
            u64 b2[4];
            b2[0] = *(u64*)&bf0.x;  b2[1] = *(u64*)&bf0.z;
            b2[2] = *(u64*)&bf1.x;  b2[3] = *(u64*)&bf1.z;
            #pragma unroll
            for (int mi = 0; mi < 4; mi++)
                #pragma unroll
                for (int nj = 0; nj < 4; nj++)
                    fma2(ch[mi][nj], a2[mi], b2[nj]);
        }

        if (kt == HALF_KT - 1) {
            // end of slice 0: bank the partial, restart the chain for slice 1
            #pragma unroll
            for (int mi = 0; mi < 4; mi++)
                #pragma unroll
                for (int nj = 0; nj < 4; nj++) {
                    tot[mi][nj] = ch[mi][nj];
                    ch[mi][nj]  = 0ull;
                }
        }

        if (more) {
            // store into the other buffer (disjoint from the one just read;
            // end-of-iteration barrier orders its reuse)
            float va[4] = {pa.x, pa.y, pa.z, pa.w};
            float wa[4] = {pb.x, pb.y, pb.z, pb.w};
            #pragma unroll
            for (int j = 0; j < 4; j++) {
                As[nxt][kq + j][frow] = va[j];
                Bs[nxt][kq + j][frow] = wa[j];
            }
            __syncthreads();
        }
    }

    // combine slices: dot = slice0 + slice1 (single correctly-rounded add)
    // then epilogue: (dot + b1) + bias1 — left-assoc
    const float bsc = bias1[0];
    const int gn0 = bn * BN + tn0;
    const int gn1 = bn * BN + tn1;
    float b1v[8];
    #pragma unroll
    for (int j = 0; j < 4; j++) { b1v[j] = b1[gn0 + j]; b1v[4 + j] = b1[gn1 + j]; }

    #pragma unroll
    for (int mi = 0; mi < 4; mi++) {
        const size_t gm = (size_t)bm * BM + tm + mi;
        float o[8];
        #pragma unroll
        for (int nj = 0; nj < 4; nj++) {
            u64 dot2 = add2(tot[mi][nj], ch[mi][nj]);   // p0 + p1
            float2 f = *reinterpret_cast<float2*>(&dot2);
            o[2*nj]   = fadd(fadd(f.x, b1v[2*nj]),   bsc);
            o[2*nj+1] = fadd(fadd(f.y, b1v[2*nj+1]), bsc);
        }
        *(float4*)(C + gm * NN + gn0) = make_float4(o[0], o[1], o[2], o[3]);
        *(float4*)(C + gm * NN + gn1) = make_float4(o[4], o[5], o[6], o[7]);
    }
}

// ---------------------------------------------------------------------------
// LIF scan, plain fp32, FMA-CONTRACTED (FROZEN — matches reference):
//   mem = fma(beta, mem, cur) - reset ; spk = (mem - 1 > 0)
// ---------------------------------------------------------------------------
__device__ __forceinline__ void lif_scan(float* p, size_t stride, float beta)
{
    float mem = 0.f;
    #pragma unroll 8
    for (int t = 0; t < TT; t++) {
        float c = p[(size_t)t * stride];
        float r = (mem > 1.0f) ? 1.0f : 0.0f;   // reset from previous mem
        mem = fsub(ffma(beta, mem, c), r);      // fma(B,mem,cur) - reset
        p[(size_t)t * stride] = (fsub(mem, 1.0f) > 0.f) ? 1.0f : 0.0f;
    }
}

__global__ void scan1_kernel(float* __restrict__ out)
{
    const int idx = blockIdx.x * blockDim.x + threadIdx.x;  // < B*H
    lif_scan(out + idx, (size_t)BB * HH, 0.9f);
}

__global__ void scan2_kernel(float* __restrict__ out2)
{
    const int idx = blockIdx.x * blockDim.x + threadIdx.x;
    if (idx >= BB * OO) return;
    lif_scan(out2 + idx, (size_t)BB * OO, 0.8f);
}

// ---------------------------------------------------------------------------
// GEMM2: cur2[M,10] = spk1[M,2048] * W2[10,2048]^T + b2.
// One row per thread, single accumulator, ascending-k FFMA chain (FROZEN),
// epilogue dot + b2. K tiled through smem (memory-bound on spk1 read).
// ---------------------------------------------------------------------------
#define BK2 64
__global__ __launch_bounds__(128)
void gemm2_kernel(const float* __restrict__ S,
                  const float* __restrict__ W2,
                  const float* __restrict__ b2,
                  float* __restrict__ C2)
{
    __shared__ float Ss[128][BK2 + 1];   // +1 pad -> conflict-free column reads
    __shared__ float Ws[BK2][OO];

    const int tid = threadIdx.x;
    const size_t row0 = (size_t)blockIdx.x * 128;

    float acc[OO];
    #pragma unroll
    for (int o = 0; o < OO; o++) acc[o] = 0.f;

    for (int kc = 0; kc < HH; kc += BK2) {       // ascending k blocks
        __syncthreads();
        #pragma unroll
        for (int i = 0; i < 16; i++) {           // 128x64 floats, float4 coalesced
            int f  = i * 128 + tid;
            int r  = f >> 4;
            int c4 = (f & 15) * 4;
            float4 v = *(const float4*)(S + (row0 + r) * (size_t)HH + kc + c4);
            Ss[r][c4]   = v.x;
            Ss[r][c4+1] = v.y;
            Ss[r][c4+2] = v.z;
            Ss[r][c4+3] = v.w;
        }
        #pragma unroll
        for (int i = 0; i < 5; i++) {            // 640 = 64*10 W2 elems
            int idx = i * 128 + tid;
            int k = idx / OO, o = idx % OO;
            Ws[k][o] = W2[(size_t)o * HH + kc + k];
        }
        __syncthreads();
        #pragma unroll 4
        for (int k = 0; k < BK2; k++) {          // ascending k within block
            float s = Ss[tid][k];
            #pragma unroll
            for (int o = 0; o < OO; o++)
                acc[o] = ffma(s, Ws[k][o], acc[o]);
        }
    }
    #pragma unroll
    for (int o = 0; o < OO; o++)
        C2[(row0 + tid) * OO + o] = fadd(acc[o], b2[o]);
}

// ---------------------------------------------------------------------------
// d_in order (setup_inputs dict order): x, W1, b1, bias1, W2, b2, T
// d_out layout: spk1_rec [T,B,H] followed by spk2_rec [T,B,O]
// ---------------------------------------------------------------------------
extern "C" void kernel_launch(void* const* d_in, const int* in_sizes, int n_in,
                              void* d_out, int out_size)
{
    const float* x     = (const float*)d_in[0];
    const float* W1    = (const float*)d_in[1];
    const float* b1    = (const float*)d_in[2];
    const float* bias1 = (const float*)d_in[3];
    const float* W2    = (const float*)d_in[4];
    const float* b2    = (const float*)d_in[5];

    float* out  = (float*)d_out;
    float* out2 = out + (size_t)TT * BB * HH;

    dim3 g1(NN / BN, MM / BM);                 // (16, 256)
    gemm1_kernel<<<g1, 512>>>(x, W1, b1, bias1, out);
    scan1_kernel<<<(BB * HH) / 256, 256>>>(out);
    gemm2_kernel<<<MM / 128, 128>>>(out, W2, b2, out2);
    scan2_kernel<<<(BB * OO + 255) / 256, 256>>>(out2);
}